// round 5
// baseline (speedup 1.0000x reference)
#include <cuda_runtime.h>
#include <cuda_bf16.h>

// Problem constants
#define H   256
#define H2  512      // 2*H
#define V   8192
#define S   4096

typedef unsigned long long ull;

// ---------------- intermediates (device globals; no allocation) ----------------
__device__ float g_q[H];            // Wa@hidden + Wa_b + Ua_b
__device__ float g_Epart[2 * S];    // attention scores, split over 2 h-halves
__device__ float g_aij[S];          // softmax weights
__device__ float g_Ci[H2];          // context vector (atomic-accumulated)
__device__ float g_z[H];
__device__ float g_r[H];
__device__ float g_hpart[H];        // Uh@y + Uh_b + Ch@Ci + Ch_b
__device__ float g_hnew[H];
__device__ float g_logits[V];

// ---------------- helpers ----------------
__device__ __forceinline__ void fma2(ull &d, ull a, ull b) {
    asm("fma.rn.f32x2 %0, %1, %2, %0;" : "+l"(d) : "l"(a), "l"(b));
}
__device__ __forceinline__ ull pack2(float x, float y) {
    ull r; asm("mov.b64 %0, {%1, %2};" : "=l"(r) : "f"(x), "f"(y)); return r;
}
__device__ __forceinline__ void unpack2(ull v, float &x, float &y) {
    asm("mov.b64 {%0, %1}, %2;" : "=f"(x), "=f"(y) : "l"(v));
}
__device__ __forceinline__ float warp_sum(float v) {
    #pragma unroll
    for (int o = 16; o; o >>= 1) v += __shfl_down_sync(0xffffffffu, v, o);
    return v;
}
__device__ __forceinline__ float dot4(float4 a, float4 b) {
    return a.x * b.x + a.y * b.y + a.z * b.z + a.w * b.w;
}

struct Params {
    const int*   tok;
    const float* hidden;
    const float* enc;
    const float* emb;
    const float *Uz, *Uzb, *Wz, *Wzb, *Cz, *Czb;
    const float *Ur, *Urb, *Wr, *Wrb, *Cr, *Crb;
    const float *Uh, *Uhb, *Wh, *Whb, *Ch, *Chb;
    const float *Ua, *Uab, *Wa, *Wab, *Va, *Vab;
    const float *Vw, *Vb;
    float* out;
};

// ---------------- K1: q[h] = Wa@hidden + Wa_b + Ua_b ----------------
__global__ void k1_prep(Params p) {
    int h = threadIdx.x;                     // 256 threads
    const float4* W4 = (const float4*)(p.Wa + h * H);
    const float4* h4 = (const float4*)p.hidden;
    float acc = 0.f;
    #pragma unroll 8
    for (int i = 0; i < H / 4; ++i) acc += dot4(W4[i], h4[i]);
    g_q[h] = acc + p.Wab[h] + p.Uab[h];
}

// ---------------- K2: attention scores (536M-FMA GEMM, fused tanh+Va) ------
// grid (64, 2): blockIdx.x -> 64-row s tile, blockIdx.y -> 128-col h half.
// 128 threads: hx = tid&15 owns h-pairs {2hx+32j, 2hx+32j+1}, sy = tid>>4 owns
// s = sy*8..sy*8+7. f32x2 accumulators packed along h.
#define KC    32
#define HPAD  130
#define SPAD  66

__global__ __launch_bounds__(128) void k2_scores(Params p) {
    __shared__ __align__(16) float sUa[KC * HPAD];   // [k][h]
    __shared__ __align__(16) float sEnc[KC * SPAD];  // [k][s]
    __shared__ float sRed[64 * 17];

    const int tid = threadIdx.x;
    const int hx = tid & 15, sy = tid >> 4;
    const int s0 = blockIdx.x * 64;
    const int h0 = blockIdx.y * 128;

    ull acc[4][8];
    #pragma unroll
    for (int j = 0; j < 4; ++j)
        #pragma unroll
        for (int i = 0; i < 8; ++i) acc[j][i] = 0ull;

    for (int kc = 0; kc < H2; kc += KC) {
        #pragma unroll
        for (int i = tid; i < 128 * KC; i += 128) {
            int h = i >> 5, k = i & 31;
            sUa[k * HPAD + h] = p.Ua[(h0 + h) * H2 + kc + k];
        }
        #pragma unroll
        for (int i = tid; i < 64 * KC; i += 128) {
            int s = i >> 5, k = i & 31;
            sEnc[k * SPAD + s] = p.enc[(s0 + s) * H2 + kc + k];
        }
        __syncthreads();

        #pragma unroll 4
        for (int k = 0; k < KC; ++k) {
            ull ua[4];
            #pragma unroll
            for (int j = 0; j < 4; ++j)
                ua[j] = *(const ull*)&sUa[k * HPAD + 2 * hx + 32 * j];
            #pragma unroll
            for (int i = 0; i < 8; ++i) {
                float e = sEnc[k * SPAD + sy * 8 + i];
                ull ee = pack2(e, e);
                #pragma unroll
                for (int j = 0; j < 4; ++j) fma2(acc[j][i], ua[j], ee);
            }
        }
        __syncthreads();
    }

    float part[8];
    #pragma unroll
    for (int i = 0; i < 8; ++i) part[i] = 0.f;
    #pragma unroll
    for (int j = 0; j < 4; ++j) {
        int h = h0 + 2 * hx + 32 * j;
        float q0 = g_q[h], q1 = g_q[h + 1];
        float v0 = p.Va[h], v1 = p.Va[h + 1];
        #pragma unroll
        for (int i = 0; i < 8; ++i) {
            float a0, a1; unpack2(acc[j][i], a0, a1);
            part[i] += v0 * tanhf(q0 + a0) + v1 * tanhf(q1 + a1);
        }
    }
    #pragma unroll
    for (int i = 0; i < 8; ++i) sRed[(sy * 8 + i) * 17 + hx] = part[i];
    __syncthreads();
    if (tid < 64) {
        float sum = 0.f;
        #pragma unroll
        for (int x = 0; x < 16; ++x) sum += sRed[tid * 17 + x];
        g_Epart[blockIdx.y * S + s0 + tid] = sum;
    }
}

// ---------------- K3: softmax over S, write aij; also zero g_Ci ------------
__global__ __launch_bounds__(1024) void k3_softmax(Params p) {
    __shared__ float red[32];
    const int t = threadIdx.x;
    if (t < H2) g_Ci[t] = 0.f;               // reset for K4 atomics
    float v[4];
    #pragma unroll
    for (int j = 0; j < 4; ++j) {
        int i = t + j * 1024;
        v[j] = g_Epart[i] + g_Epart[S + i];
    }
    float m = fmaxf(fmaxf(v[0], v[1]), fmaxf(v[2], v[3]));
    #pragma unroll
    for (int o = 16; o; o >>= 1) m = fmaxf(m, __shfl_down_sync(0xffffffffu, m, o));
    if ((t & 31) == 0) red[t >> 5] = m;
    __syncthreads();
    if (t < 32) {
        float mm = red[t];
        #pragma unroll
        for (int o = 16; o; o >>= 1) mm = fmaxf(mm, __shfl_down_sync(0xffffffffu, mm, o));
        if (t == 0) red[0] = mm;
    }
    __syncthreads();
    m = red[0];
    __syncthreads();
    float e[4], ssum = 0.f;
    #pragma unroll
    for (int j = 0; j < 4; ++j) { e[j] = expf(v[j] - m); ssum += e[j]; }
    ssum = warp_sum(ssum);
    if ((t & 31) == 0) red[t >> 5] = ssum;
    __syncthreads();
    if (t < 32) {
        float s2 = red[t];
        s2 = warp_sum(s2);
        if (t == 0) red[0] = s2;
    }
    __syncthreads();
    float inv = 1.f / red[0];
    #pragma unroll
    for (int j = 0; j < 4; ++j) {
        int i = t + j * 1024;
        float a = e[j] * inv;
        g_aij[i] = a;
        p.out[V + H + i] = a;
    }
}

// ---------------- K4: Ci[j] = sum_s aij[s] * enc[s][j]  (REWRITTEN) --------
// 128 blocks, each owns a 32-row s-chunk and streams FULL 2048B rows
// coalesced. Thread t handles cols {2t, 2t+1} via float2. Unrolled s-loop
// gives MLP≈8; atomicAdd merges 128 partials per column.
__global__ __launch_bounds__(256) void k4_ci(Params p) {
    const int t = threadIdx.x;
    const int s0 = blockIdx.x * 32;
    float ax = 0.f, ay = 0.f;
    #pragma unroll 8
    for (int s = 0; s < 32; ++s) {
        float a = g_aij[s0 + s];
        float2 v = ((const float2*)(p.enc + (size_t)(s0 + s) * H2))[t];
        ax += a * v.x;
        ay += a * v.y;
    }
    atomicAdd(&g_Ci[2 * t],     ax);
    atomicAdd(&g_Ci[2 * t + 1], ay);
}

// ---------------- K5: gate pre-activations (block-per-row) -----------------
// 768 blocks x 128 threads; block b -> row (b&255) of matrix (b>>8).
// Per-thread: 16 independent float4 loads over the 32KB U row -> high MLP.
__global__ __launch_bounds__(128) void k5_gates(Params p) {
    __shared__ float red[4];
    const int t = threadIdx.x;
    const int mat = blockIdx.x >> 8;         // 0=z 1=r 2=h
    const int row = blockIdx.x & 255;

    const float *U, *Ub, *W, *Wb, *C, *Cb;
    if (mat == 0)      { U = p.Uz; Ub = p.Uzb; W = p.Wz; Wb = p.Wzb; C = p.Cz; Cb = p.Czb; }
    else if (mat == 1) { U = p.Ur; Ub = p.Urb; W = p.Wr; Wb = p.Wrb; C = p.Cr; Cb = p.Crb; }
    else               { U = p.Uh; Ub = p.Uhb; W = nullptr; Wb = nullptr; C = p.Ch; Cb = p.Chb; }

    const float4* y4 = (const float4*)(p.emb + (size_t)p.tok[0] * V);
    const float4* U4 = (const float4*)(U + (size_t)row * V);
    float acc = 0.f;
    #pragma unroll
    for (int i = 0; i < 16; ++i)             // V/4 = 2048, 128 threads
        acc += dot4(U4[t + i * 128], y4[t + i * 128]);

    {   // C term: H2/4 = 128 float4s, one per thread
        const float4* C4 = (const float4*)(C + row * H2);
        const float4* ci4 = (const float4*)g_Ci;
        acc += dot4(C4[t], ci4[t]);
    }
    if (mat < 2 && t < 64) {                 // W term: H/4 = 64 float4s
        const float4* W4 = (const float4*)(W + row * H);
        const float4* h4 = (const float4*)p.hidden;
        acc += dot4(W4[t], h4[t]);
    }
    acc = warp_sum(acc);
    if ((t & 31) == 0) red[t >> 5] = acc;
    __syncthreads();
    if (t == 0) {
        float total = red[0] + red[1] + red[2] + red[3]
                    + Ub[row] + Cb[row] + (mat < 2 ? Wb[row] : 0.f);
        if (mat == 0)      g_z[row] = 1.f / (1.f + expf(-total));
        else if (mat == 1) g_r[row] = 1.f / (1.f + expf(-total));
        else               g_hpart[row] = total;
    }
}

// ---------------- K6: c & hidden_new ----------------
__global__ __launch_bounds__(256) void k6_hnew(Params p) {
    __shared__ __align__(16) float rh[H];
    const int t = threadIdx.x;
    rh[t] = g_r[t] * p.hidden[t];
    __syncthreads();
    const float4* W4 = (const float4*)(p.Wh + t * H);
    const float4* r4 = (const float4*)rh;
    float acc = 0.f;
    #pragma unroll 8
    for (int i = 0; i < H / 4; ++i) acc += dot4(W4[i], r4[i]);
    float c = tanhf(g_hpart[t] + p.Whb[t] + acc);
    float z = g_z[t];
    float hn = (1.f - z) * c + z * p.hidden[t];
    g_hnew[t] = hn;
    p.out[V + t] = hn;
}

// ---------------- K7: logits = V_w @ hidden_new + V_b ----------------------
// 256 blocks x 256 threads; warp handles 4 rows, loads batched before
// reductions so memory overlaps the shuffle chains.
__global__ __launch_bounds__(256) void k7_logits(Params p) {
    __shared__ __align__(16) float sh[H];
    const int t = threadIdx.x;
    if (t < H) sh[t] = g_hnew[t];
    __syncthreads();
    const int wid = t >> 5, lane = t & 31;
    const int row0 = blockIdx.x * 32 + wid * 4;
    const float4* h4 = (const float4*)sh;

    float4 a[4], b[4];
    #pragma unroll
    for (int r = 0; r < 4; ++r) {
        const float4* V4 = (const float4*)(p.Vw + (size_t)(row0 + r) * H);
        a[r] = V4[lane];
        b[r] = V4[lane + 32];
    }
    #pragma unroll
    for (int r = 0; r < 4; ++r) {
        float acc = dot4(a[r], h4[lane]) + dot4(b[r], h4[lane + 32]);
        acc = warp_sum(acc);
        if (lane == 0) g_logits[row0 + r] = acc + p.Vb[row0 + r];
    }
}

// ---------------- K8: log_softmax over V ----------------
__global__ __launch_bounds__(1024) void k8_logsoftmax(Params p) {
    __shared__ float red[32];
    const int t = threadIdx.x;
    float v[8];
    float m = -1e30f;
    #pragma unroll
    for (int j = 0; j < 8; ++j) { v[j] = g_logits[t + j * 1024]; m = fmaxf(m, v[j]); }
    #pragma unroll
    for (int o = 16; o; o >>= 1) m = fmaxf(m, __shfl_down_sync(0xffffffffu, m, o));
    if ((t & 31) == 0) red[t >> 5] = m;
    __syncthreads();
    if (t < 32) {
        float mm = red[t];
        #pragma unroll
        for (int o = 16; o; o >>= 1) mm = fmaxf(mm, __shfl_down_sync(0xffffffffu, mm, o));
        if (t == 0) red[0] = mm;
    }
    __syncthreads();
    m = red[0];
    __syncthreads();
    float ssum = 0.f;
    #pragma unroll
    for (int j = 0; j < 8; ++j) ssum += expf(v[j] - m);
    ssum = warp_sum(ssum);
    if ((t & 31) == 0) red[t >> 5] = ssum;
    __syncthreads();
    if (t < 32) {
        float s2 = red[t];
        s2 = warp_sum(s2);
        if (t == 0) red[0] = s2;
    }
    __syncthreads();
    float lse = m + logf(red[0]);
    #pragma unroll
    for (int j = 0; j < 8; ++j) p.out[t + j * 1024] = v[j] - lse;
}

// ---------------- launch ----------------
extern "C" void kernel_launch(void* const* d_in, const int* in_sizes, int n_in,
                              void* d_out, int out_size) {
    (void)in_sizes; (void)n_in; (void)out_size;
    Params p;
    p.tok    = (const int*)  d_in[0];
    p.hidden = (const float*)d_in[1];
    p.enc    = (const float*)d_in[2];
    p.emb    = (const float*)d_in[3];
    p.Uz  = (const float*)d_in[4];  p.Uzb = (const float*)d_in[5];
    p.Wz  = (const float*)d_in[6];  p.Wzb = (const float*)d_in[7];
    p.Cz  = (const float*)d_in[8];  p.Czb = (const float*)d_in[9];
    p.Ur  = (const float*)d_in[10]; p.Urb = (const float*)d_in[11];
    p.Wr  = (const float*)d_in[12]; p.Wrb = (const float*)d_in[13];
    p.Cr  = (const float*)d_in[14]; p.Crb = (const float*)d_in[15];
    p.Uh  = (const float*)d_in[16]; p.Uhb = (const float*)d_in[17];
    p.Wh  = (const float*)d_in[18]; p.Whb = (const float*)d_in[19];
    p.Ch  = (const float*)d_in[20]; p.Chb = (const float*)d_in[21];
    p.Ua  = (const float*)d_in[22]; p.Uab = (const float*)d_in[23];
    p.Wa  = (const float*)d_in[24]; p.Wab = (const float*)d_in[25];
    p.Va  = (const float*)d_in[26]; p.Vab = (const float*)d_in[27];
    p.Vw  = (const float*)d_in[28]; p.Vb  = (const float*)d_in[29];
    p.out = (float*)d_out;

    k1_prep<<<1, 256>>>(p);
    k2_scores<<<dim3(64, 2), 128>>>(p);
    k3_softmax<<<1, 1024>>>(p);
    k4_ci<<<128, 256>>>(p);
    k5_gates<<<768, 128>>>(p);
    k6_hnew<<<1, 256>>>(p);
    k7_logits<<<256, 256>>>(p);
    k8_logsoftmax<<<1, 1024>>>(p);
}

// round 6
// speedup vs baseline: 1.8380x; 1.8380x over previous
#include <cuda_runtime.h>
#include <cuda_bf16.h>

// Problem constants
#define H   256
#define H2  512      // 2*H
#define V   8192
#define S   4096

typedef unsigned long long ull;

// ---------------- intermediates (device globals; no allocation) ----------------
__device__ float g_q[H];            // Wa@hidden + Wa_b + Ua_b
__device__ float g_Epart[4 * S];    // attention scores, split over 4 h-quarters
__device__ float g_aij[S];          // softmax weights
__device__ float g_Ci[H2];          // context vector (atomic-accumulated)
__device__ float g_acc[3 * H];      // gate pre-activation accumulators (z|r|h)
__device__ float g_hnew[H];
__device__ float g_logits[V];

// ---------------- helpers ----------------
__device__ __forceinline__ void fma2(ull &d, ull a, ull b) {
    asm("fma.rn.f32x2 %0, %1, %2, %0;" : "+l"(d) : "l"(a), "l"(b));
}
__device__ __forceinline__ ull pack2(float x, float y) {
    ull r; asm("mov.b64 %0, {%1, %2};" : "=l"(r) : "f"(x), "f"(y)); return r;
}
__device__ __forceinline__ void unpack2(ull v, float &x, float &y) {
    asm("mov.b64 {%0, %1}, %2;" : "=f"(x), "=f"(y) : "l"(v));
}
__device__ __forceinline__ float warp_sum(float v) {
    #pragma unroll
    for (int o = 16; o; o >>= 1) v += __shfl_down_sync(0xffffffffu, v, o);
    return v;
}
__device__ __forceinline__ float dot4(float4 a, float4 b) {
    return a.x * b.x + a.y * b.y + a.z * b.z + a.w * b.w;
}

struct Params {
    const int*   tok;
    const float* hidden;
    const float* enc;
    const float* emb;
    const float *Uz, *Uzb, *Wz, *Wzb, *Cz, *Czb;
    const float *Ur, *Urb, *Wr, *Wrb, *Cr, *Crb;
    const float *Uh, *Uhb, *Wh, *Whb, *Ch, *Chb;
    const float *Ua, *Uab, *Wa, *Wab, *Va, *Vab;
    const float *Vw, *Vb;
    float* out;
};

// ---------------- K1: q[row] = Wa@hidden + Wa_b + Ua_b  (block-per-row) ----
__global__ __launch_bounds__(64) void k1_prep(Params p) {
    __shared__ float red[2];
    const int row = blockIdx.x, t = threadIdx.x;
    float acc = dot4(((const float4*)(p.Wa + row * H))[t],
                     ((const float4*)p.hidden)[t]);
    acc = warp_sum(acc);
    if ((t & 31) == 0) red[t >> 5] = acc;
    __syncthreads();
    if (t == 0) g_q[row] = red[0] + red[1] + p.Wab[row] + p.Uab[row];
}

// ---------------- K2: attention scores (536M-FMA GEMM, fused tanh+Va) ------
// grid (64, 4): blockIdx.x -> 64-row s tile, blockIdx.y -> 64-col h quarter.
// 128 threads: hx = tid&15 owns h-pairs {2hx+32j}, sy = tid>>4 owns 8 s-rows.
// f32x2 accumulators packed along h. ~2 CTAs/SM for latency hiding.
#define KC     32
#define HPADB  66    // 64 + 2 pad
#define SPAD   66

__global__ __launch_bounds__(128) void k2_scores(Params p) {
    __shared__ __align__(16) float sUa[KC * HPADB];  // [k][h]
    __shared__ __align__(16) float sEnc[KC * SPAD];  // [k][s]
    __shared__ float sRed[64 * 17];

    const int tid = threadIdx.x;
    const int hx = tid & 15, sy = tid >> 4;
    const int s0 = blockIdx.x * 64;
    const int h0 = blockIdx.y * 64;

    ull acc[2][8];
    #pragma unroll
    for (int j = 0; j < 2; ++j)
        #pragma unroll
        for (int i = 0; i < 8; ++i) acc[j][i] = 0ull;

    for (int kc = 0; kc < H2; kc += KC) {
        // load Ua tile (64h x KC), transposed into smem (2048 elems / 128 thr)
        #pragma unroll
        for (int i = tid; i < 64 * KC; i += 128) {
            int h = i >> 5, k = i & 31;
            sUa[k * HPADB + h] = p.Ua[(h0 + h) * H2 + kc + k];
        }
        // load enc tile (64s x KC), transposed
        #pragma unroll
        for (int i = tid; i < 64 * KC; i += 128) {
            int s = i >> 5, k = i & 31;
            sEnc[k * SPAD + s] = p.enc[(s0 + s) * H2 + kc + k];
        }
        __syncthreads();

        #pragma unroll 4
        for (int k = 0; k < KC; ++k) {
            ull ua0 = *(const ull*)&sUa[k * HPADB + 2 * hx];
            ull ua1 = *(const ull*)&sUa[k * HPADB + 2 * hx + 32];
            #pragma unroll
            for (int i = 0; i < 8; ++i) {
                float e = sEnc[k * SPAD + sy * 8 + i];
                ull ee = pack2(e, e);
                fma2(acc[0][i], ua0, ee);
                fma2(acc[1][i], ua1, ee);
            }
        }
        __syncthreads();
    }

    // finalize: part[s] = sum_{h in quarter} Va[h] * tanh(q[h] + acc)
    float part[8];
    #pragma unroll
    for (int i = 0; i < 8; ++i) part[i] = 0.f;
    #pragma unroll
    for (int j = 0; j < 2; ++j) {
        int h = h0 + 2 * hx + 32 * j;
        float q0 = g_q[h], q1 = g_q[h + 1];
        float v0 = p.Va[h], v1 = p.Va[h + 1];
        #pragma unroll
        for (int i = 0; i < 8; ++i) {
            float a0, a1; unpack2(acc[j][i], a0, a1);
            part[i] += v0 * tanhf(q0 + a0) + v1 * tanhf(q1 + a1);
        }
    }
    #pragma unroll
    for (int i = 0; i < 8; ++i) sRed[(sy * 8 + i) * 17 + hx] = part[i];
    __syncthreads();
    if (tid < 64) {
        float sum = 0.f;
        #pragma unroll
        for (int x = 0; x < 16; ++x) sum += sRed[tid * 17 + x];
        g_Epart[blockIdx.y * S + s0 + tid] = sum;
    }
}

// ---------------- K3: softmax over S; zero g_Ci and g_acc ------------------
__global__ __launch_bounds__(1024) void k3_softmax(Params p) {
    __shared__ float red[32];
    const int t = threadIdx.x;
    if (t < H2) g_Ci[t] = 0.f;
    if (t < 3 * H) g_acc[t] = 0.f;
    float v[4];
    #pragma unroll
    for (int j = 0; j < 4; ++j) {
        int i = t + j * 1024;
        v[j] = g_Epart[i] + g_Epart[S + i] + g_Epart[2 * S + i] + g_Epart[3 * S + i];
    }
    float m = fmaxf(fmaxf(v[0], v[1]), fmaxf(v[2], v[3]));
    #pragma unroll
    for (int o = 16; o; o >>= 1) m = fmaxf(m, __shfl_down_sync(0xffffffffu, m, o));
    if ((t & 31) == 0) red[t >> 5] = m;
    __syncthreads();
    if (t < 32) {
        float mm = red[t];
        #pragma unroll
        for (int o = 16; o; o >>= 1) mm = fmaxf(mm, __shfl_down_sync(0xffffffffu, mm, o));
        if (t == 0) red[0] = mm;
    }
    __syncthreads();
    m = red[0];
    __syncthreads();
    float e[4], ssum = 0.f;
    #pragma unroll
    for (int j = 0; j < 4; ++j) { e[j] = expf(v[j] - m); ssum += e[j]; }
    ssum = warp_sum(ssum);
    if ((t & 31) == 0) red[t >> 5] = ssum;
    __syncthreads();
    if (t < 32) {
        float s2 = red[t];
        s2 = warp_sum(s2);
        if (t == 0) red[0] = s2;
    }
    __syncthreads();
    float inv = 1.f / red[0];
    #pragma unroll
    for (int j = 0; j < 4; ++j) {
        int i = t + j * 1024;
        float a = e[j] * inv;
        g_aij[i] = a;
        p.out[V + H + i] = a;
    }
}

// ---------------- K4: Ci[j] = sum_s aij[s] * enc[s][j] ---------------------
// 256 blocks x 16 s-rows, full 2048B coalesced rows, atomic merge.
__global__ __launch_bounds__(256) void k4_ci(Params p) {
    const int t = threadIdx.x;
    const int s0 = blockIdx.x * 16;
    float ax = 0.f, ay = 0.f;
    #pragma unroll
    for (int s = 0; s < 16; ++s) {
        float a = g_aij[s0 + s];
        float2 v = ((const float2*)(p.enc + (size_t)(s0 + s) * H2))[t];
        ax += a * v.x;
        ay += a * v.y;
    }
    atomicAdd(&g_Ci[2 * t],     ax);
    atomicAdd(&g_Ci[2 * t + 1], ay);
}

// ---------------- K5: gate pre-activations (split-K atomic GEMV) -----------
// blocks [0,3072): U-chunks  (row = b>>2, 8KB chunk = b&3, 2 float4/thread)
// blocks [3072,3584): W terms (z,r rows, 256 cols)
// blocks [3584,4352): C terms (all rows, 512 cols)
// Each block reduces and atomicAdds into g_acc[grow].
__global__ __launch_bounds__(256) void k5_gates(Params p) {
    __shared__ float red[8];
    const int t = threadIdx.x;
    const int b = blockIdx.x;
    float acc = 0.f;
    int grow;
    if (b < 3072) {
        grow = b >> 2;
        const int chunk = b & 3;
        const int row = grow & 255;
        const float* U = (grow < 256) ? p.Uz : (grow < 512) ? p.Ur : p.Uh;
        const float4* U4 = (const float4*)(U + (size_t)row * V) + chunk * 512;
        const float4* y4 = (const float4*)(p.emb + (size_t)p.tok[0] * V) + chunk * 512;
        float4 u0 = U4[t], u1 = U4[t + 256];
        float4 a0 = y4[t], a1 = y4[t + 256];
        acc = dot4(u0, a0) + dot4(u1, a1);
    } else if (b < 3584) {
        const int w = b - 3072;              // 0..511  (z:0-255, r:256-511)
        grow = w;
        const int row = w & 255;
        const float* W = (w < 256) ? p.Wz : p.Wr;
        if (t < 64)
            acc = dot4(((const float4*)(W + row * H))[t],
                       ((const float4*)p.hidden)[t]);
    } else {
        const int c = b - 3584;              // 0..767
        grow = c;
        const int row = c & 255;
        const float* C = (c < 256) ? p.Cz : (c < 512) ? p.Cr : p.Ch;
        if (t < 128)
            acc = dot4(((const float4*)(C + row * H2))[t],
                       ((const float4*)g_Ci)[t]);
    }
    acc = warp_sum(acc);
    if ((t & 31) == 0) red[t >> 5] = acc;
    __syncthreads();
    if (t == 0) {
        float s = red[0] + red[1] + red[2] + red[3]
                + red[4] + red[5] + red[6] + red[7];
        atomicAdd(&g_acc[grow], s);
    }
}

// ---------------- K6: gates -> c -> hidden_new -----------------------------
__global__ __launch_bounds__(256) void k6_hnew(Params p) {
    __shared__ __align__(16) float rh[H];
    const int t = threadIdx.x;
    float z = 1.f / (1.f + expf(-(g_acc[t] + p.Uzb[t] + p.Wzb[t] + p.Czb[t])));
    float r = 1.f / (1.f + expf(-(g_acc[H + t] + p.Urb[t] + p.Wrb[t] + p.Crb[t])));
    float hv = p.hidden[t];
    rh[t] = r * hv;
    __syncthreads();
    const float4* W4 = (const float4*)(p.Wh + t * H);
    const float4* r4 = (const float4*)rh;
    float acc = 0.f;
    #pragma unroll 8
    for (int i = 0; i < H / 4; ++i) acc += dot4(W4[i], r4[i]);
    float c = tanhf(g_acc[2 * H + t] + p.Uhb[t] + p.Chb[t] + p.Whb[t] + acc);
    float hn = (1.f - z) * c + z * hv;
    g_hnew[t] = hn;
    p.out[V + t] = hn;
}

// ---------------- K7: logits = V_w @ hidden_new + V_b ----------------------
__global__ __launch_bounds__(256) void k7_logits(Params p) {
    __shared__ __align__(16) float sh[H];
    const int t = threadIdx.x;
    if (t < H) sh[t] = g_hnew[t];
    __syncthreads();
    const int wid = t >> 5, lane = t & 31;
    const int row0 = blockIdx.x * 32 + wid * 4;
    const float4* h4 = (const float4*)sh;

    float4 a[4], b[4];
    #pragma unroll
    for (int r = 0; r < 4; ++r) {
        const float4* V4 = (const float4*)(p.Vw + (size_t)(row0 + r) * H);
        a[r] = V4[lane];
        b[r] = V4[lane + 32];
    }
    #pragma unroll
    for (int r = 0; r < 4; ++r) {
        float acc = dot4(a[r], h4[lane]) + dot4(b[r], h4[lane + 32]);
        acc = warp_sum(acc);
        if (lane == 0) g_logits[row0 + r] = acc + p.Vb[row0 + r];
    }
}

// ---------------- K8: log_softmax over V ----------------
__global__ __launch_bounds__(1024) void k8_logsoftmax(Params p) {
    __shared__ float red[32];
    const int t = threadIdx.x;
    float v[8];
    float m = -1e30f;
    #pragma unroll
    for (int j = 0; j < 8; ++j) { v[j] = g_logits[t + j * 1024]; m = fmaxf(m, v[j]); }
    #pragma unroll
    for (int o = 16; o; o >>= 1) m = fmaxf(m, __shfl_down_sync(0xffffffffu, m, o));
    if ((t & 31) == 0) red[t >> 5] = m;
    __syncthreads();
    if (t < 32) {
        float mm = red[t];
        #pragma unroll
        for (int o = 16; o; o >>= 1) mm = fmaxf(mm, __shfl_down_sync(0xffffffffu, mm, o));
        if (t == 0) red[0] = mm;
    }
    __syncthreads();
    m = red[0];
    __syncthreads();
    float ssum = 0.f;
    #pragma unroll
    for (int j = 0; j < 8; ++j) ssum += expf(v[j] - m);
    ssum = warp_sum(ssum);
    if ((t & 31) == 0) red[t >> 5] = ssum;
    __syncthreads();
    if (t < 32) {
        float s2 = red[t];
        s2 = warp_sum(s2);
        if (t == 0) red[0] = s2;
    }
    __syncthreads();
    float lse = m + logf(red[0]);
    #pragma unroll
    for (int j = 0; j < 8; ++j) p.out[t + j * 1024] = v[j] - lse;
}

// ---------------- launch ----------------
extern "C" void kernel_launch(void* const* d_in, const int* in_sizes, int n_in,
                              void* d_out, int out_size) {
    (void)in_sizes; (void)n_in; (void)out_size;
    Params p;
    p.tok    = (const int*)  d_in[0];
    p.hidden = (const float*)d_in[1];
    p.enc    = (const float*)d_in[2];
    p.emb    = (const float*)d_in[3];
    p.Uz  = (const float*)d_in[4];  p.Uzb = (const float*)d_in[5];
    p.Wz  = (const float*)d_in[6];  p.Wzb = (const float*)d_in[7];
    p.Cz  = (const float*)d_in[8];  p.Czb = (const float*)d_in[9];
    p.Ur  = (const float*)d_in[10]; p.Urb = (const float*)d_in[11];
    p.Wr  = (const float*)d_in[12]; p.Wrb = (const float*)d_in[13];
    p.Cr  = (const float*)d_in[14]; p.Crb = (const float*)d_in[15];
    p.Uh  = (const float*)d_in[16]; p.Uhb = (const float*)d_in[17];
    p.Wh  = (const float*)d_in[18]; p.Whb = (const float*)d_in[19];
    p.Ch  = (const float*)d_in[20]; p.Chb = (const float*)d_in[21];
    p.Ua  = (const float*)d_in[22]; p.Uab = (const float*)d_in[23];
    p.Wa  = (const float*)d_in[24]; p.Wab = (const float*)d_in[25];
    p.Va  = (const float*)d_in[26]; p.Vab = (const float*)d_in[27];
    p.Vw  = (const float*)d_in[28]; p.Vb  = (const float*)d_in[29];
    p.out = (float*)d_out;

    k1_prep<<<256, 64>>>(p);
    k2_scores<<<dim3(64, 4), 128>>>(p);
    k3_softmax<<<1, 1024>>>(p);
    k4_ci<<<256, 256>>>(p);
    k5_gates<<<4352, 256>>>(p);
    k6_hnew<<<1, 256>>>(p);
    k7_logits<<<256, 256>>>(p);
    k8_logsoftmax<<<1, 1024>>>(p);
}